// round 2
// baseline (speedup 1.0000x reference)
#include <cuda_runtime.h>
#include <math.h>

#define BH   64      // B*H
#define NB   32      // buckets
#define BSZ  128     // tokens per bucket
#define DHD  64      // head dim
#define TPB  (BSZ*DHD)   // 8192 floats per bucket tile

typedef unsigned long long u64;

// ---- packed f32x2 helpers (Blackwell FFMA2 path; exact fp32 semantics) ----
__device__ __forceinline__ u64 f2_fma(u64 a, u64 b, u64 c) {
    u64 d; asm("fma.rn.f32x2 %0,%1,%2,%3;" : "=l"(d) : "l"(a), "l"(b), "l"(c)); return d;
}
__device__ __forceinline__ u64 f2_mul(u64 a, u64 b) {
    u64 d; asm("mul.rn.f32x2 %0,%1,%2;" : "=l"(d) : "l"(a), "l"(b)); return d;
}
__device__ __forceinline__ u64 f2_pack(float lo, float hi) {
    u64 d; asm("mov.b64 %0,{%1,%2};" : "=l"(d) : "f"(lo), "f"(hi)); return d;
}
__device__ __forceinline__ float2 f2_unpack(u64 v) {
    float2 r; asm("mov.b64 {%0,%1},%2;" : "=f"(r.x), "=f"(r.y) : "l"(v)); return r;
}

// Scratch (allocation-free rule: __device__ globals)
__device__ float g_R[BH*NB*NB];                       // 256 KB
__device__ float g_bkr[BH*NB*DHD];                    // 512 KB bucket key sums
__device__ float g_kre[(size_t)BH*NB*BSZ*DHD];        // 64 MB
__device__ float g_vre[(size_t)BH*NB*BSZ*DHD];        // 64 MB

// ---------------------------------------------------------------------------
// Kernel 0: bucket key sums  (full-chip parallel DRAM read of K)
// grid (NB, BH), block 256: tid -> (part=tid>>6 in 0..3, d=tid&63)
// ---------------------------------------------------------------------------
__global__ void __launch_bounds__(256)
bucket_sum_kernel(const float* __restrict__ k)
{
    int u  = blockIdx.x;
    int bh = blockIdx.y;
    int d    = threadIdx.x & 63;
    int part = threadIdx.x >> 6;

    __shared__ float red[4][DHD];

    const float* kp = k + (size_t)bh * NB * TPB + (size_t)u * TPB
                        + (size_t)part * 32 * DHD + d;
    float s = 0.f;
    #pragma unroll 8
    for (int t = 0; t < 32; t++) s += kp[t * DHD];
    red[part][d] = s;
    __syncthreads();
    if (part == 0) {
        g_bkr[(bh * NB + u) * DHD + d] = red[0][d] + red[1][d] + red[2][d] + red[3][d];
    }
}

// ---------------------------------------------------------------------------
// Kernel 1: routing logits -> 7 Sinkhorn iters -> exp -> strict lower tri.
// One block per bh, 1024 threads = (u,j).
// ---------------------------------------------------------------------------
__global__ void __launch_bounds__(1024)
sinkhorn_kernel(const float* __restrict__ sort_w,
                const float* __restrict__ gum)
{
    int bh  = blockIdx.x;
    int tid = threadIdx.x;

    __shared__ float bkr[NB][DHD];      // bucket key sums (32x64)
    __shared__ float ews[DHD][NB];      // sort_w slice    (64x32)
    __shared__ float smx[NB][NB + 1];   // column-reduction scratch

    int h = bh & 15;   // sort_w broadcast over batch
    #pragma unroll
    for (int rep = 0; rep < 2; rep++) {
        int idx = tid + rep * 1024;
        ((float*)bkr)[idx] = g_bkr[bh * (NB * DHD) + idx];
        ((float*)ews)[idx] = sort_w[h * (DHD * NB) + idx];
    }
    __syncthreads();

    int u = tid >> 5;   // row (warp == row)
    int j = tid & 31;   // col (lane)

    float r = 0.f;
    #pragma unroll
    for (int d = 0; d < DHD; d++) r += bkr[u][d] * ews[d][j];
    r = logf(fmaxf(r, 0.f) + 1e-6f);
    r = (r + gum[bh * 1024 + tid]) * (1.0f / 0.75f);

    for (int it = 0; it < 7; it++) {
        // row logsumexp via warp shuffles
        float m = r;
        #pragma unroll
        for (int off = 16; off > 0; off >>= 1)
            m = fmaxf(m, __shfl_xor_sync(0xffffffffu, m, off));
        float se = __expf(r - m);
        #pragma unroll
        for (int off = 16; off > 0; off >>= 1)
            se += __shfl_xor_sync(0xffffffffu, se, off);
        r -= m + logf(se);

        // column logsumexp via smem
        smx[u][j] = r;
        __syncthreads();
        float cm = -3.0e38f;
        #pragma unroll
        for (int vv = 0; vv < NB; vv++) cm = fmaxf(cm, smx[vv][j]);
        float cs = 0.f;
        #pragma unroll
        for (int vv = 0; vv < NB; vv++) cs += __expf(smx[vv][j] - cm);
        r -= cm + logf(cs);
        __syncthreads();
    }

    r = __expf(r);
    if (j >= u) r = 0.f;           // tril(R, -1)
    g_R[bh * 1024 + tid] = r;
}

// ---------------------------------------------------------------------------
// Kernel 2: soft permutation  k_re = R @ Kmat, v_re = R @ Vmat.
// Block = (col-tile of 256, bh); all 32 output rows per block (K/V read once).
// Packed f32x2: 16 accumulators over output-row pairs; R prepacked in smem.
// R is strictly lower triangular so looping all v is numerically identical.
// ---------------------------------------------------------------------------
__global__ void __launch_bounds__(256)
permute_kernel(const float* __restrict__ k, const float* __restrict__ v)
{
    int tilec = blockIdx.x;   // 0..31
    int bh    = blockIdx.y;
    int c     = threadIdx.x;  // 0..255

    __shared__ u64 RsP[NB][16];            // RsP[v][p] = (R[2p][v], R[2p+1][v])
    __shared__ __align__(16) float T[NB][256];

    const float* gR = g_R + bh * 1024;
    #pragma unroll
    for (int rep = 0; rep < 2; rep++) {
        int idx = c + rep * 256;           // 512 entries
        int vv = idx >> 4, p = idx & 15;
        RsP[vv][p] = f2_pack(gR[(2*p) * NB + vv], gR[(2*p+1) * NB + vv]);
    }

    size_t base = (size_t)bh * NB * TPB + (size_t)tilec * 256 + c;

    // ---- K ----
    #pragma unroll
    for (int vv = 0; vv < NB; vv++) T[vv][c] = k[base + (size_t)vv * TPB];
    __syncthreads();

    u64 acc[16];
    #pragma unroll
    for (int p = 0; p < 16; p++) acc[p] = 0ULL;
    #pragma unroll
    for (int vv = 0; vv < NB; vv++) {
        float x = T[vv][c];
        u64 x2 = f2_pack(x, x);
        #pragma unroll
        for (int p = 0; p < 16; p++) acc[p] = f2_fma(x2, RsP[vv][p], acc[p]);
    }
    #pragma unroll
    for (int p = 0; p < 16; p++) {
        float2 a = f2_unpack(acc[p]);
        g_kre[base + (size_t)(2*p)   * TPB] = a.x;
        g_kre[base + (size_t)(2*p+1) * TPB] = a.y;
    }
    __syncthreads();

    // ---- V ----
    #pragma unroll
    for (int vv = 0; vv < NB; vv++) T[vv][c] = v[base + (size_t)vv * TPB];
    __syncthreads();

    #pragma unroll
    for (int p = 0; p < 16; p++) acc[p] = 0ULL;
    #pragma unroll
    for (int vv = 0; vv < NB; vv++) {
        float x = T[vv][c];
        u64 x2 = f2_pack(x, x);
        #pragma unroll
        for (int p = 0; p < 16; p++) acc[p] = f2_fma(x2, RsP[vv][p], acc[p]);
    }
    #pragma unroll
    for (int p = 0; p < 16; p++) {
        float2 a = f2_unpack(acc[p]);
        g_vre[base + (size_t)(2*p)   * TPB] = a.x;
        g_vre[base + (size_t)(2*p+1) * TPB] = a.y;
    }
}

// ---------------------------------------------------------------------------
// Kernel 3: per-(bh, bucket) attention. 128 q x 256 k x 64 d, flash-style
// online softmax in 16-key groups, all inner math in packed f32x2.
// ---------------------------------------------------------------------------
__global__ void __launch_bounds__(128)
attn_kernel(const float* __restrict__ q,
            const float* __restrict__ k,
            const float* __restrict__ v,
            float* __restrict__ out)
{
    int u  = blockIdx.x;   // bucket
    int bh = blockIdx.y;
    int i  = threadIdx.x;  // query 0..127

    const size_t base = (size_t)bh * NB * TPB + (size_t)u * TPB;

    __shared__ __align__(16) float Ks[64][DHD];
    __shared__ __align__(16) float Vs[64][DHD];

    // query row (64 floats) as 32 packed f32x2
    u64 q2[32];
    {
        const ulonglong2* qp = (const ulonglong2*)(q + base + (size_t)i * DHD);
        #pragma unroll
        for (int d = 0; d < 16; d++) {
            ulonglong2 t = qp[d];
            q2[2*d]   = t.x;
            q2[2*d+1] = t.y;
        }
    }

    u64 o2[32];
    #pragma unroll
    for (int d = 0; d < 32; d++) o2[d] = 0ULL;
    float m = -3.0e38f, l = 0.f;

    for (int tile = 0; tile < 4; tile++) {
        const float* ksrc;
        const float* vsrc;
        if (tile < 2) {
            size_t off = base + (size_t)tile * 64 * DHD;
            ksrc = g_kre + off;
            vsrc = g_vre + off;
        } else {
            size_t off = base + (size_t)(tile - 2) * 64 * DHD;
            ksrc = k + off;
            vsrc = v + off;
        }
        __syncthreads();
        {
            const float4* kp4 = (const float4*)ksrc;
            const float4* vp4 = (const float4*)vsrc;
            float4* Ks4 = (float4*)Ks;
            float4* Vs4 = (float4*)Vs;
            #pragma unroll
            for (int r = 0; r < 8; r++) {
                Ks4[i + r * 128] = kp4[i + r * 128];
                Vs4[i + r * 128] = vp4[i + r * 128];
            }
        }
        __syncthreads();

        #pragma unroll
        for (int jj = 0; jj < 64; jj += 16) {
            float s[16];
            #pragma unroll
            for (int a = 0; a < 16; a++) {
                const ulonglong2* krow = (const ulonglong2*)Ks[jj + a];
                u64 acc0 = 0ULL, acc1 = 0ULL;
                #pragma unroll
                for (int d = 0; d < 16; d++) {
                    ulonglong2 kk = krow[d];
                    acc0 = f2_fma(q2[2*d],   kk.x, acc0);
                    acc1 = f2_fma(q2[2*d+1], kk.y, acc1);
                }
                float2 a0 = f2_unpack(acc0);
                float2 a1 = f2_unpack(acc1);
                s[a] = (a0.x + a0.y + a1.x + a1.y) * 0.03125f;  // 1/sqrt(1024)
            }
            float mt = s[0];
            #pragma unroll
            for (int a = 1; a < 16; a++) mt = fmaxf(mt, s[a]);
            float mnew = fmaxf(m, mt);
            float corr = __expf(m - mnew);
            l *= corr;
            u64 corr2 = f2_pack(corr, corr);
            #pragma unroll
            for (int d = 0; d < 32; d++) o2[d] = f2_mul(o2[d], corr2);
            float p[16];
            #pragma unroll
            for (int a = 0; a < 16; a++) { p[a] = __expf(s[a] - mnew); l += p[a]; }
            m = mnew;
            #pragma unroll
            for (int a = 0; a < 16; a++) {
                u64 p2 = f2_pack(p[a], p[a]);
                const ulonglong2* vrow = (const ulonglong2*)Vs[jj + a];
                #pragma unroll
                for (int d = 0; d < 16; d++) {
                    ulonglong2 vv = vrow[d];
                    o2[2*d]   = f2_fma(p2, vv.x, o2[2*d]);
                    o2[2*d+1] = f2_fma(p2, vv.y, o2[2*d+1]);
                }
            }
        }
    }

    float inv = 1.f / l;
    u64 inv2 = f2_pack(inv, inv);
    ulonglong2* op = (ulonglong2*)(out + base + (size_t)i * DHD);
    #pragma unroll
    for (int d = 0; d < 16; d++) {
        ulonglong2 t;
        t.x = f2_mul(o2[2*d],   inv2);
        t.y = f2_mul(o2[2*d+1], inv2);
        op[d] = t;
    }
}

// ---------------------------------------------------------------------------
extern "C" void kernel_launch(void* const* d_in, const int* in_sizes, int n_in,
                              void* d_out, int out_size)
{
    const float* q   = (const float*)d_in[0];
    const float* k   = (const float*)d_in[1];
    const float* v   = (const float*)d_in[2];
    const float* sw  = (const float*)d_in[3];
    const float* gum = (const float*)d_in[4];
    float* out = (float*)d_out;

    dim3 g0(NB, BH);
    bucket_sum_kernel<<<g0, 256>>>(k);

    sinkhorn_kernel<<<BH, 1024>>>(sw, gum);

    dim3 g2(NB, BH);
    permute_kernel<<<g2, 256>>>(k, v);

    dim3 g3(NB, BH);
    attn_kernel<<<g3, 128>>>(q, k, v, out);
}